// round 14
// baseline (speedup 1.0000x reference)
#include <cuda_runtime.h>
#include <math.h>
#include <stdint.h>

// Problem constants
#define BATCH 2
#define SEQ 2048
#define DM 2048
#define NH 16
#define HD 128
#define NQKV ((NH + 2*NH) * HD)   // 6144
#define NTOK (BATCH * SEQ)        // 4096

// Scratch (allocation-free rule: __device__ globals)
__device__ float g_qkv[(size_t)NTOK * NQKV];        // 96 MB
__device__ float g_attn[(size_t)NTOK * (NH * HD)];  // 32 MB
__device__ float g_hid_t[(size_t)NTOK * DM];        // 32 MB
__device__ float g_wqkv_t[(size_t)DM * NQKV];       // 48 MB  [N][K] transposed+rounded
__device__ float g_wo_t[(size_t)DM * DM];           // 16 MB  [N][K] transposed+rounded

// ---------------------------------------------------------------------------
// helpers
// ---------------------------------------------------------------------------
__device__ __forceinline__ unsigned cvt_tf32(float x) {
    unsigned u;
    asm("cvt.rna.tf32.f32 %0, %1;" : "=r"(u) : "f"(x));
    return u;
}
__device__ __forceinline__ float rnd_tf32(float x) {
    return __uint_as_float(cvt_tf32(x));
}

__device__ __forceinline__ void mma_m16n8k8(float* c, const unsigned* a, const unsigned* b) {
    asm volatile(
        "mma.sync.aligned.m16n8k8.row.col.f32.tf32.tf32.f32 "
        "{%0,%1,%2,%3}, {%4,%5,%6,%7}, {%8,%9}, {%0,%1,%2,%3};"
        : "+f"(c[0]), "+f"(c[1]), "+f"(c[2]), "+f"(c[3])
        : "r"(a[0]), "r"(a[1]), "r"(a[2]), "r"(a[3]), "r"(b[0]), "r"(b[1]));
}

__device__ __forceinline__ void cp16(void* dst_smem, const void* src) {
    unsigned d = (unsigned)__cvta_generic_to_shared(dst_smem);
    asm volatile("cp.async.cg.shared.global [%0], [%1], 16;" :: "r"(d), "l"(src));
}
__device__ __forceinline__ void cp_commit() {
    asm volatile("cp.async.commit_group;");
}
template<int N>
__device__ __forceinline__ void cp_wait() {
    asm volatile("cp.async.wait_group %0;" :: "n"(N));
}
__device__ __forceinline__ uint32_t smem_u32(const void* p) {
    uint32_t a;
    asm("{ .reg .u64 t; cvta.to.shared.u64 t, %1; cvt.u32.u64 %0, t; }" : "=r"(a) : "l"(p));
    return a;
}
__device__ __forceinline__ void ldsm_x4(unsigned& r0, unsigned& r1, unsigned& r2,
                                        unsigned& r3, uint32_t addr) {
    asm volatile("ldmatrix.sync.aligned.m8n8.x4.shared.b16 {%0,%1,%2,%3}, [%4];"
                 : "=r"(r0), "=r"(r1), "=r"(r2), "=r"(r3) : "r"(addr));
}

// ---------------------------------------------------------------------------
// tf32 pre-rounding (vectorized)
// ---------------------------------------------------------------------------
__global__ void round_tf32_kernel(const float4* __restrict__ in,
                                  float4* __restrict__ out, int n4)
{
    int i = blockIdx.x * 256 + threadIdx.x;
    if (i < n4) {
        float4 v = in[i];
        out[i] = make_float4(rnd_tf32(v.x), rnd_tf32(v.y), rnd_tf32(v.z), rnd_tf32(v.w));
    }
}

// ---------------------------------------------------------------------------
// transpose + tf32 round: in [R][C] -> out [C][R]
// ---------------------------------------------------------------------------
__global__ void transpose_round_kernel(const float* __restrict__ in,
                                       float* __restrict__ out, int R, int C)
{
    __shared__ float tile[32][33];
    const int c0 = blockIdx.x * 32;
    const int r0 = blockIdx.y * 32;
    const int tx = threadIdx.x;
#pragma unroll
    for (int i = threadIdx.y; i < 32; i += 8)
        tile[i][tx] = in[(size_t)(r0 + i) * C + c0 + tx];
    __syncthreads();
#pragma unroll
    for (int i = threadIdx.y; i < 32; i += 8)
        out[(size_t)(c0 + i) * R + r0 + tx] = rnd_tf32(tile[tx][i]);
}

// ---------------------------------------------------------------------------
// TF32 GEMM v4 (ldmatrix, wide tile): C[M,N] = A[M,K] * B[N,K]^T
//   CTA tile 128x256x32, 3-stage cp.async, 256 threads, 1 CTA/SM.
//   Warp tile 64x64 (warps 2x4). Halves sync events per unit output vs v3.
// ---------------------------------------------------------------------------
#define GSTR 36
#define STG_W (384 * GSTR)                 // (128 A-rows + 256 B-rows) * 36
#define GEMM_SMEM (3 * STG_W * 4)          // 165888 bytes

__global__ __launch_bounds__(256, 1) void gemm_tf32(
    const float* __restrict__ A, const float* __restrict__ B,
    float* __restrict__ C, int M, int N, int K)
{
    extern __shared__ float sm[];
    const uint32_t smb = smem_u32(sm);

    const int tid = threadIdx.x;
    const int wid = tid >> 5;
    const int lane = tid & 31;
    const int g = lane >> 2;
    const int t = lane & 3;
    const int warp_m = wid & 1;    // 0..1 (64 rows)
    const int warp_n = wid >> 1;   // 0..3 (64 cols)

    const float* Ab = A + (size_t)(blockIdx.y * 128) * K;
    const float* Bb = B + (size_t)(blockIdx.x * 256) * K;

    float acc[4][8][4];
#pragma unroll
    for (int mi = 0; mi < 4; mi++)
#pragma unroll
        for (int nj = 0; nj < 8; nj++)
#pragma unroll
            for (int r = 0; r < 4; r++) acc[mi][nj][r] = 0.f;

    const int KT = K >> 5;

#define GEMM_ISSUE(stage, kt)                                                   \
    do {                                                                        \
        float* as_ = sm + (stage) * STG_W;                                      \
        float* bs_ = as_ + 128 * GSTR;                                          \
        const float* ag_ = Ab + (size_t)(kt) * 32;                              \
        const float* bg_ = Bb + (size_t)(kt) * 32;                              \
        int r0_ = tid >> 3, c_ = (tid & 7) * 4;                                 \
        _Pragma("unroll")                                                       \
        for (int i = 0; i < 4; i++) {                                           \
            int r_ = r0_ + i * 32;                                              \
            cp16(&as_[r_ * GSTR + c_], ag_ + (size_t)r_ * K + c_);              \
        }                                                                       \
        _Pragma("unroll")                                                       \
        for (int i = 0; i < 8; i++) {                                           \
            int r_ = r0_ + i * 32;                                              \
            cp16(&bs_[r_ * GSTR + c_], bg_ + (size_t)r_ * K + c_);              \
        }                                                                       \
    } while (0)

    GEMM_ISSUE(0, 0); cp_commit();
    GEMM_ISSUE(1, 1); cp_commit();

    const int a_row = ((lane >> 3) & 1) * 8 + (lane & 7);
    const int a_col = (lane >= 16) ? 4 : 0;
    const int b_row = (lane & 7) + ((lane >= 16) ? 8 : 0);
    const int b_col = ((lane >> 3) & 1) * 4;

    for (int kt = 0; kt < KT; kt++) {
        cp_wait<1>();
        __syncthreads();

        if (kt + 2 < KT) GEMM_ISSUE((kt + 2) % 3, kt + 2);
        cp_commit();

        const uint32_t as_u = smb + ((kt % 3) * STG_W) * 4;
        const uint32_t bs_u = as_u + 128 * GSTR * 4;
        const uint32_t abase = as_u + (uint32_t)((warp_m * 64 + a_row) * GSTR + a_col) * 4;
        const uint32_t bbase = bs_u + (uint32_t)((warp_n * 64 + b_row) * GSTR + b_col) * 4;

#pragma unroll
        for (int ks = 0; ks < 4; ks++) {
            const int kk = ks * 8;
            unsigned am[4][4], bn[8][2];
#pragma unroll
            for (int mi = 0; mi < 4; mi++)
                ldsm_x4(am[mi][0], am[mi][1], am[mi][2], am[mi][3],
                        abase + (uint32_t)(mi * 16 * GSTR + kk) * 4);
#pragma unroll
            for (int hseg = 0; hseg < 4; hseg++) {
                unsigned r0, r1, r2, r3;
                ldsm_x4(r0, r1, r2, r3,
                        bbase + (uint32_t)(hseg * 16 * GSTR + kk) * 4);
                bn[hseg * 2][0] = r0;     bn[hseg * 2][1] = r1;
                bn[hseg * 2 + 1][0] = r2; bn[hseg * 2 + 1][1] = r3;
            }
#pragma unroll
            for (int mi = 0; mi < 4; mi++)
#pragma unroll
                for (int nj = 0; nj < 8; nj++)
                    mma_m16n8k8(acc[mi][nj], am[mi], bn[nj]);
        }
    }

#pragma unroll
    for (int mi = 0; mi < 4; mi++) {
#pragma unroll
        for (int nj = 0; nj < 8; nj++) {
            int r0 = blockIdx.y * 128 + warp_m * 64 + mi * 16 + g;
            int c0 = blockIdx.x * 256 + warp_n * 64 + nj * 8 + 2 * t;
            *(float2*)(C + (size_t)r0 * N + c0) = make_float2(acc[mi][nj][0], acc[mi][nj][1]);
            *(float2*)(C + (size_t)(r0 + 8) * N + c0) = make_float2(acc[mi][nj][2], acc[mi][nj][3]);
        }
    }
}

// ---------------------------------------------------------------------------
// RoPE + tf32 round. q,k heads: rope in place. v heads: round + hd-permute.
// ---------------------------------------------------------------------------
__global__ void rope_kernel(float* __restrict__ qkv,
                            const float* __restrict__ cosp,
                            const float* __restrict__ sinp)
{
    const int tk = blockIdx.x;
    const int hh = blockIdx.y;        // 0..47
    const int d = threadIdx.x;        // 0..63
    const int s = tk & (SEQ - 1);

    float* p = qkv + (size_t)tk * NQKV + hh * HD;
    float x1 = p[d];
    float x2 = p[d + 64];
    if (hh < 2 * NH) {
        float c1 = cosp[s * HD + d];
        float c2 = cosp[s * HD + d + 64];
        float s1 = sinp[s * HD + d];
        float s2 = sinp[s * HD + d + 64];
        p[d]      = rnd_tf32(x1 * c1 - x2 * s1);
        p[d + 64] = rnd_tf32(x2 * c2 + x1 * s2);
    } else {
        __syncthreads();
        int y1 = (d & 7) * 16 + (d >> 3);            // v_perm(d)
        int y2 = y1 + 8;                             // v_perm(d+64)
        p[y1] = rnd_tf32(x1);
        p[y2] = rnd_tf32(x2);
    }
}

// ---------------------------------------------------------------------------
// Flash attention v6 (R12 known-best): software-pipelined, BQ=64, BKV=32,
// 4 warps, 2 CTAs/SM, LDSM K-frags, guarded rescale.
// ---------------------------------------------------------------------------
#define F3_STR 132
#define F3_BUF (32 * F3_STR)
#define FLASH3_SMEM (4 * F3_BUF * 4)   // 67584 bytes
#define NTILE3 (SEQ / 32)

__global__ __launch_bounds__(128, 2) void flash6_tf32(
    const float* __restrict__ qkv, float* __restrict__ out)
{
    extern __shared__ float sf[];
    const uint32_t sfb = smem_u32(sf);

    const int tid = threadIdx.x;
    const int wid = tid >> 5;
    const int lane = tid & 31;
    const int g = lane >> 2;
    const int t = lane & 3;
    const unsigned FULL = 0xffffffffu;

    const int b = blockIdx.y >> 4;
    const int h = blockIdx.y & 15;
    const int q0 = blockIdx.x * 64;
    const float scale = 0.08838834764831845f;  // 1/sqrt(128)

    const float* qbase = qkv + (size_t)(b * SEQ + q0 + wid * 16) * NQKV + h * HD;
    const float* kbase = qkv + (size_t)(b * SEQ) * NQKV + (NH + h) * HD;
    const float* vbase = qkv + (size_t)(b * SEQ) * NQKV + (2 * NH + h) * HD;

    unsigned qa[16][4];
#pragma unroll
    for (int ks = 0; ks < 16; ks++) {
        int kk = ks * 8;
        qa[ks][0] = __float_as_uint(qbase[(size_t)g * NQKV + kk + t]);
        qa[ks][1] = __float_as_uint(qbase[(size_t)(g + 8) * NQKV + kk + t]);
        qa[ks][2] = __float_as_uint(qbase[(size_t)g * NQKV + kk + t + 4]);
        qa[ks][3] = __float_as_uint(qbase[(size_t)(g + 8) * NQKV + kk + t + 4]);
    }

    float oacc[16][4];
#pragma unroll
    for (int ni = 0; ni < 16; ni++)
#pragma unroll
        for (int r = 0; r < 4; r++) oacc[ni][r] = 0.f;

    float m0 = -INFINITY, m1 = -INFINITY, l0 = 0.f, l1 = 0.f;

    const int b_row = (lane & 7) + ((lane >= 16) ? 8 : 0);
    const int b_col = ((lane >> 3) & 1) * 4;
    const uint32_t kfrag0 = sfb + (uint32_t)(b_row * F3_STR + b_col) * 4;

    float sa[4][4], sb[4][4];

#define F6_ISSUE(bufofs, base, kt)                                               \
    do {                                                                         \
        float* buf_ = sf + (bufofs);                                             \
        _Pragma("unroll")                                                        \
        for (int i = 0; i < 8; i++) {                                            \
            int idx = tid + 128 * i;                                             \
            int r_ = idx >> 5, c_ = (idx & 31) * 4;                              \
            cp16(&buf_[r_ * F3_STR + c_],                                        \
                 (base) + (size_t)((kt) * 32 + r_) * NQKV + c_);                 \
        }                                                                        \
    } while (0)

#define F6_SMMA(S_, kt)                                                          \
    do {                                                                         \
        const uint32_t kfb_ = kfrag0 + (uint32_t)(((kt) & 1) * F3_BUF) * 4;      \
        _Pragma("unroll")                                                        \
        for (int nj = 0; nj < 4; nj++)                                           \
            _Pragma("unroll")                                                    \
            for (int r = 0; r < 4; r++) S_[nj][r] = 0.f;                         \
        _Pragma("unroll")                                                        \
        for (int ks = 0; ks < 16; ks++) {                                        \
            const int kk = ks * 8;                                               \
            unsigned bn[4][2];                                                   \
            {                                                                    \
                unsigned r0, r1, r2, r3;                                         \
                ldsm_x4(r0, r1, r2, r3, kfb_ + (uint32_t)kk * 4);                \
                bn[0][0] = r0; bn[0][1] = r1; bn[1][0] = r2; bn[1][1] = r3;      \
                ldsm_x4(r0, r1, r2, r3, kfb_ + (uint32_t)(16 * F3_STR + kk) * 4);\
                bn[2][0] = r0; bn[2][1] = r1; bn[3][0] = r2; bn[3][1] = r3;      \
            }                                                                    \
            _Pragma("unroll")                                                    \
            for (int nj = 0; nj < 4; nj++)                                       \
                mma_m16n8k8(S_[nj], qa[ks], bn[nj]);                             \
        }                                                                        \
    } while (0)

#define F6_SOFTMAX(S_)                                                           \
    do {                                                                         \
        float mx0 = -INFINITY, mx1 = -INFINITY;                                  \
        _Pragma("unroll")                                                        \
        for (int j = 0; j < 4; j++) {                                            \
            S_[j][0] *= scale; S_[j][1] *= scale;                                \
            S_[j][2] *= scale; S_[j][3] *= scale;                                \
            mx0 = fmaxf(mx0, fmaxf(S_[j][0], S_[j][1]));                         \
            mx1 = fmaxf(mx1, fmaxf(S_[j][2], S_[j][3]));                         \
        }                                                                        \
        mx0 = fmaxf(mx0, __shfl_xor_sync(FULL, mx0, 1));                         \
        mx0 = fmaxf(mx0, __shfl_xor_sync(FULL, mx0, 2));                         \
        mx1 = fmaxf(mx1, __shfl_xor_sync(FULL, mx1, 1));                         \
        mx1 = fmaxf(mx1, __shfl_xor_sync(FULL, mx1, 2));                         \
        float mn0 = fmaxf(m0, mx0), mn1 = fmaxf(m1, mx1);                        \
        float a0 = __expf(m0 - mn0), a1 = __expf(m1 - mn1);                      \
        float s0 = 0.f, s1 = 0.f;                                                \
        _Pragma("unroll")                                                        \
        for (int j = 0; j < 4; j++) {                                            \
            float p00 = __expf(S_[j][0] - mn0);                                  \
            float p01 = __expf(S_[j][1] - mn0);                                  \
            float p10 = __expf(S_[j][2] - mn1);                                  \
            float p11 = __expf(S_[j][3] - mn1);                                  \
            s0 += p00 + p01;                                                     \
            s1 += p10 + p11;                                                     \
            S_[j][0] = __uint_as_float(cvt_tf32(p00));                           \
            S_[j][1] = __uint_as_float(cvt_tf32(p01));                           \
            S_[j][2] = __uint_as_float(cvt_tf32(p10));                           \
            S_[j][3] = __uint_as_float(cvt_tf32(p11));                           \
        }                                                                        \
        s0 += __shfl_xor_sync(FULL, s0, 1);                                      \
        s0 += __shfl_xor_sync(FULL, s0, 2);                                      \
        s1 += __shfl_xor_sync(FULL, s1, 1);                                      \
        s1 += __shfl_xor_sync(FULL, s1, 2);                                      \
        l0 = l0 * a0 + s0;                                                       \
        l1 = l1 * a1 + s1;                                                       \
        m0 = mn0; m1 = mn1;                                                      \
        if (a0 != 1.f || a1 != 1.f) {                                            \
            _Pragma("unroll")                                                    \
            for (int ni = 0; ni < 16; ni++) {                                    \
                oacc[ni][0] *= a0; oacc[ni][1] *= a0;                            \
                oacc[ni][2] *= a1; oacc[ni][3] *= a1;                            \
            }                                                                    \
        }                                                                        \
    } while (0)

#define F6_PV(S_, kt)                                                            \
    do {                                                                         \
        const float* Vs_ = sf + (2 + ((kt) & 1)) * F3_BUF;                       \
        const int sl = (lane & ~3) | (t >> 1);                                   \
        _Pragma("unroll")                                                        \
        for (int j = 0; j < 4; j++) {                                            \
            float x0  = __shfl_sync(FULL, S_[j][0], sl);                         \
            float x1  = __shfl_sync(FULL, S_[j][1], sl);                         \
            float y0  = __shfl_sync(FULL, S_[j][2], sl);                         \
            float y1  = __shfl_sync(FULL, S_[j][3], sl);                         \
            float x0b = __shfl_sync(FULL, S_[j][0], sl + 2);                     \
            float x1b = __shfl_sync(FULL, S_[j][1], sl + 2);                     \
            float y0b = __shfl_sync(FULL, S_[j][2], sl + 2);                     \
            float y1b = __shfl_sync(FULL, S_[j][3], sl + 2);                     \
            unsigned pa[4];                                                      \
            pa[0] = __float_as_uint((t & 1) ? x1  : x0);                         \
            pa[1] = __float_as_uint((t & 1) ? y1  : y0);                         \
            pa[2] = __float_as_uint((t & 1) ? x1b : x0b);                        \
            pa[3] = __float_as_uint((t & 1) ? y1b : y0b);                        \
            const float* vr0 = Vs_ + (j * 8 + t) * F3_STR + g * 16;              \
            const float* vr1 = Vs_ + (j * 8 + t + 4) * F3_STR + g * 16;          \
            _Pragma("unroll")                                                    \
            for (int q = 0; q < 4; q++) {                                        \
                const uint4 v0 = *(const uint4*)(vr0 + q * 4);                   \
                const uint4 v1 = *(const uint4*)(vr1 + q * 4);                   \
                const unsigned vv[4][2] = {                                      \
                    {v0.x, v1.x}, {v0.y, v1.y}, {v0.z, v1.z}, {v0.w, v1.w}};     \
                _Pragma("unroll")                                                \
                for (int i = 0; i < 4; i++)                                      \
                    mma_m16n8k8(oacc[q * 4 + i], pa, vv[i]);                     \
            }                                                                    \
        }                                                                        \
    } while (0)

#define F6_STEP(CUR, NXT, kt)                                                    \
    do {                                                                         \
        cp_wait<1>(); __syncthreads();            /* K(kt+1) ready */            \
        if ((kt) + 1 < NTILE3) {                                                 \
            F6_SMMA(NXT, (kt) + 1);                                              \
            if ((kt) + 2 < NTILE3)                                               \
                F6_ISSUE(((kt) & 1) * F3_BUF, kbase, (kt) + 2);                  \
        }                                                                        \
        cp_commit();                                                             \
        F6_SOFTMAX(CUR);                                                         \
        cp_wait<1>(); __syncthreads();            /* V(kt) ready */              \
        F6_PV(CUR, kt);                                                          \
        if ((kt) + 1 < NTILE3)                                                   \
            F6_ISSUE((2 + (((kt) + 1) & 1)) * F3_BUF, vbase, (kt) + 1);          \
        cp_commit();                                                             \
    } while (0)

    // prologue: K0 -> wait -> S(0) -> issue K1, V0
    F6_ISSUE(0, kbase, 0); cp_commit();
    cp_wait<0>(); __syncthreads();
    F6_SMMA(sa, 0);
    __syncthreads();                               // all warps done reading K0
    F6_ISSUE(F3_BUF, kbase, 1); cp_commit();       // K1
    F6_ISSUE(2 * F3_BUF, vbase, 0); cp_commit();   // V0

    for (int kt = 0; kt < NTILE3; kt += 2) {
        F6_STEP(sa, sb, kt);
        F6_STEP(sb, sa, kt + 1);
    }

    // ---- epilogue: normalize + tf32-round + write (true hd layout) ----
    float li0 = 1.0f / l0, li1 = 1.0f / l1;
    const int r0 = q0 + wid * 16 + g;
    float* o0 = out + (size_t)(b * SEQ + r0) * (NH * HD) + h * HD;
    float* o1 = out + (size_t)(b * SEQ + r0 + 8) * (NH * HD) + h * HD;
#pragma unroll
    for (int ni = 0; ni < 16; ni++) {
        int nc = ni * 8 + 2 * t;
        *(float2*)(o0 + nc) = make_float2(rnd_tf32(oacc[ni][0] * li0),
                                          rnd_tf32(oacc[ni][1] * li0));
        *(float2*)(o1 + nc) = make_float2(rnd_tf32(oacc[ni][2] * li1),
                                          rnd_tf32(oacc[ni][3] * li1));
    }
}

// ---------------------------------------------------------------------------
extern "C" void kernel_launch(void* const* d_in, const int* in_sizes, int n_in,
                              void* d_out, int out_size)
{
    const float* hidden = (const float*)d_in[0];
    const float* cosp   = (const float*)d_in[1];
    const float* sinp   = (const float*)d_in[2];
    const float* wqkv   = (const float*)d_in[3];
    const float* wo     = (const float*)d_in[4];
    float* out = (float*)d_out;

    void *p0, *p1, *p2, *p3, *p4;
    cudaGetSymbolAddress(&p0, g_qkv);
    cudaGetSymbolAddress(&p1, g_attn);
    cudaGetSymbolAddress(&p2, g_hid_t);
    cudaGetSymbolAddress(&p3, g_wqkv_t);
    cudaGetSymbolAddress(&p4, g_wo_t);
    float* qkv    = (float*)p0;
    float* attn   = (float*)p1;
    float* hid_t  = (float*)p2;
    float* wqkv_t = (float*)p3;
    float* wo_t   = (float*)p4;

    static bool attr_set = false;
    if (!attr_set) {
        cudaFuncSetAttribute(flash6_tf32, cudaFuncAttributeMaxDynamicSharedMemorySize, FLASH3_SMEM);
        cudaFuncSetAttribute(gemm_tf32, cudaFuncAttributeMaxDynamicSharedMemorySize, GEMM_SMEM);
        attr_set = true;
    }

    dim3 tpb(32, 8);

    // 0) prep: round hidden; transpose+round weights to [N][K]
    {
        int n4h = NTOK * DM / 4;
        round_tf32_kernel<<<n4h / 256, 256>>>((const float4*)hidden, (float4*)hid_t, n4h);
        transpose_round_kernel<<<dim3(NQKV / 32, DM / 32), tpb>>>(wqkv, wqkv_t, DM, NQKV);
        transpose_round_kernel<<<dim3(DM / 32, DM / 32), tpb>>>(wo, wo_t, DM, DM);
    }
    // 1) QKV projection: [4096,2048] x [6144,2048]^T, tile 128x256
    {
        dim3 grid(NQKV / 256, NTOK / 128);   // 24 x 32
        gemm_tf32<<<grid, 256, GEMM_SMEM>>>(hid_t, wqkv_t, qkv, NTOK, NQKV, DM);
    }
    // 2) RoPE (+ V hd-permute)
    {
        dim3 grid(NTOK, 3 * NH);
        rope_kernel<<<grid, 64>>>(qkv, cosp, sinp);
    }
    // 3) Flash attention (R12 flash6, 2 CTAs/SM)
    {
        dim3 grid(SEQ / 64, BATCH * NH);   // 32 x 32
        flash6_tf32<<<grid, 128, FLASH3_SMEM>>>(qkv, attn);
    }
    // 4) Output projection: tile 128x256
    {
        dim3 grid(DM / 256, NTOK / 128);   // 8 x 32
        gemm_tf32<<<grid, 256, GEMM_SMEM>>>(attn, wo_t, out, NTOK, DM, NH * HD);
    }
}

// round 15
// speedup vs baseline: 1.8259x; 1.8259x over previous
#include <cuda_runtime.h>
#include <cuda_fp16.h>
#include <math.h>
#include <stdint.h>

// Problem constants
#define BATCH 2
#define SEQ 2048
#define DM 2048
#define NH 16
#define HD 128
#define NQKV ((NH + 2*NH) * HD)   // 6144
#define NTOK (BATCH * SEQ)        // 4096

// Scratch (allocation-free rule: __device__ globals)
__device__ float  g_qkv[(size_t)NTOK * NQKV];        // 96 MB (f32 gemm out)
__device__ __half g_qkvh[(size_t)NTOK * NQKV];       // 48 MB (roped fp16)
__device__ __half g_attnh[(size_t)NTOK * (NH * HD)]; // 16 MB
__device__ __half g_hidh[(size_t)NTOK * DM];         // 16 MB
__device__ __half g_wqkvh[(size_t)DM * NQKV];        // 24 MB [N][K]
__device__ __half g_woh[(size_t)DM * DM];            //  8 MB [N][K]

// ---------------------------------------------------------------------------
// helpers
// ---------------------------------------------------------------------------
__device__ __forceinline__ unsigned pack_h2(float lo, float hi) {
    unsigned d;
    asm("cvt.rn.f16x2.f32 %0, %1, %2;" : "=r"(d) : "f"(hi), "f"(lo));
    return d;
}

__device__ __forceinline__ void mma_f16(float* c, const unsigned* a, const unsigned* b) {
    asm volatile(
        "mma.sync.aligned.m16n8k16.row.col.f32.f16.f16.f32 "
        "{%0,%1,%2,%3}, {%4,%5,%6,%7}, {%8,%9}, {%0,%1,%2,%3};"
        : "+f"(c[0]), "+f"(c[1]), "+f"(c[2]), "+f"(c[3])
        : "r"(a[0]), "r"(a[1]), "r"(a[2]), "r"(a[3]), "r"(b[0]), "r"(b[1]));
}

__device__ __forceinline__ void cp16(void* dst_smem, const void* src) {
    unsigned d = (unsigned)__cvta_generic_to_shared(dst_smem);
    asm volatile("cp.async.cg.shared.global [%0], [%1], 16;" :: "r"(d), "l"(src));
}
__device__ __forceinline__ void cp_commit() {
    asm volatile("cp.async.commit_group;");
}
template<int N>
__device__ __forceinline__ void cp_wait() {
    asm volatile("cp.async.wait_group %0;" :: "n"(N));
}
__device__ __forceinline__ uint32_t smem_u32(const void* p) {
    uint32_t a;
    asm("{ .reg .u64 t; cvta.to.shared.u64 t, %1; cvt.u32.u64 %0, t; }" : "=r"(a) : "l"(p));
    return a;
}
__device__ __forceinline__ void ldsm_x4(unsigned& r0, unsigned& r1, unsigned& r2,
                                        unsigned& r3, uint32_t addr) {
    asm volatile("ldmatrix.sync.aligned.m8n8.x4.shared.b16 {%0,%1,%2,%3}, [%4];"
                 : "=r"(r0), "=r"(r1), "=r"(r2), "=r"(r3) : "r"(addr));
}
__device__ __forceinline__ void ldsm_x4_t(unsigned& r0, unsigned& r1, unsigned& r2,
                                          unsigned& r3, uint32_t addr) {
    asm volatile("ldmatrix.sync.aligned.m8n8.x4.trans.shared.b16 {%0,%1,%2,%3}, [%4];"
                 : "=r"(r0), "=r"(r1), "=r"(r2), "=r"(r3) : "r"(addr));
}

// ---------------------------------------------------------------------------
// f32 -> f16 conversion (vectorized)
// ---------------------------------------------------------------------------
__global__ void round_f16_kernel(const float4* __restrict__ in,
                                 uint2* __restrict__ out, int n4)
{
    int i = blockIdx.x * 256 + threadIdx.x;
    if (i < n4) {
        float4 v = in[i];
        out[i] = make_uint2(pack_h2(v.x, v.y), pack_h2(v.z, v.w));
    }
}

// ---------------------------------------------------------------------------
// transpose + f16 convert: in f32 [R][C] -> out f16 [C][R]
// ---------------------------------------------------------------------------
__global__ void transpose_f16_kernel(const float* __restrict__ in,
                                     __half* __restrict__ out, int R, int C)
{
    __shared__ float tile[32][33];
    const int c0 = blockIdx.x * 32;
    const int r0 = blockIdx.y * 32;
    const int tx = threadIdx.x;
#pragma unroll
    for (int i = threadIdx.y; i < 32; i += 8)
        tile[i][tx] = in[(size_t)(r0 + i) * C + c0 + tx];
    __syncthreads();
#pragma unroll
    for (int i = threadIdx.y; i < 32; i += 8)
        out[(size_t)(c0 + i) * R + r0 + tx] = __float2half_rn(tile[tx][i]);
}

// ---------------------------------------------------------------------------
// FP16 GEMM: C[M,N](f32) = A[M,K](f16) * B[N,K](f16)^T
//   CTA tile 128x128x64, 3-stage cp.async, 256 threads, 2 CTA/SM,
//   LDSM fragments, mma m16n8k16.
// ---------------------------------------------------------------------------
#define GSTRH 72
#define STG_H (2 * 128 * GSTRH)            // halfs per stage (A then B)
#define GEMM_SMEM (3 * STG_H * 2)          // 110592 bytes

__global__ __launch_bounds__(256, 2) void gemm_f16(
    const __half* __restrict__ A, const __half* __restrict__ B,
    float* __restrict__ C, int M, int N, int K)
{
    extern __shared__ __half smh[];
    const uint32_t smb = smem_u32(smh);

    const int tid = threadIdx.x;
    const int wid = tid >> 5;
    const int lane = tid & 31;
    const int g = lane >> 2;
    const int t = lane & 3;
    const int warp_m = wid & 1;
    const int warp_n = wid >> 1;

    const __half* Ab = A + (size_t)(blockIdx.y * 128) * K;
    const __half* Bb = B + (size_t)(blockIdx.x * 128) * K;

    float acc[4][4][4];
#pragma unroll
    for (int mi = 0; mi < 4; mi++)
#pragma unroll
        for (int nj = 0; nj < 4; nj++)
#pragma unroll
            for (int r = 0; r < 4; r++) acc[mi][nj][r] = 0.f;

    const int KT = K >> 6;

#define GEMM_ISSUE(stage, kt)                                                   \
    do {                                                                        \
        __half* as_ = smh + (stage) * STG_H;                                    \
        __half* bs_ = as_ + 128 * GSTRH;                                        \
        const __half* ag_ = Ab + (size_t)(kt) * 64;                             \
        const __half* bg_ = Bb + (size_t)(kt) * 64;                             \
        _Pragma("unroll")                                                       \
        for (int i = 0; i < 4; i++) {                                           \
            int idx = tid + 256 * i;                                            \
            int r_ = idx >> 3, c_ = (idx & 7) * 8;                              \
            cp16(&as_[r_ * GSTRH + c_], ag_ + (size_t)r_ * K + c_);             \
            cp16(&bs_[r_ * GSTRH + c_], bg_ + (size_t)r_ * K + c_);             \
        }                                                                       \
    } while (0)

    GEMM_ISSUE(0, 0); cp_commit();
    GEMM_ISSUE(1, 1); cp_commit();

    // ldmatrix lane addressing
    const int a_row = (lane & 7) + ((lane >> 3) & 1) * 8;
    const int a_colh = (lane >= 16) ? 8 : 0;
    const int b_row = (lane & 7) + ((lane >= 16) ? 8 : 0);
    const int b_colh = ((lane >> 3) & 1) * 8;

    for (int kt = 0; kt < KT; kt++) {
        cp_wait<1>();
        __syncthreads();

        if (kt + 2 < KT) GEMM_ISSUE((kt + 2) % 3, kt + 2);
        cp_commit();

        const uint32_t as_u = smb + ((kt % 3) * STG_H) * 2;
        const uint32_t bs_u = as_u + 128 * GSTRH * 2;
        const uint32_t abase = as_u + (uint32_t)((warp_m * 64 + a_row) * GSTRH + a_colh) * 2;
        const uint32_t bbase = bs_u + (uint32_t)((warp_n * 32 + b_row) * GSTRH + b_colh) * 2;

#pragma unroll
        for (int ks = 0; ks < 4; ks++) {
            const int kk = ks * 16;
            unsigned am[4][4], bn[4][2];
#pragma unroll
            for (int mi = 0; mi < 4; mi++)
                ldsm_x4(am[mi][0], am[mi][1], am[mi][2], am[mi][3],
                        abase + (uint32_t)(mi * 16 * GSTRH + kk) * 2);
            {
                unsigned r0, r1, r2, r3;
                ldsm_x4(r0, r1, r2, r3, bbase + (uint32_t)kk * 2);
                bn[0][0] = r0; bn[0][1] = r1; bn[1][0] = r2; bn[1][1] = r3;
                ldsm_x4(r0, r1, r2, r3, bbase + (uint32_t)(16 * GSTRH + kk) * 2);
                bn[2][0] = r0; bn[2][1] = r1; bn[3][0] = r2; bn[3][1] = r3;
            }
#pragma unroll
            for (int mi = 0; mi < 4; mi++)
#pragma unroll
                for (int nj = 0; nj < 4; nj++)
                    mma_f16(acc[mi][nj], am[mi], bn[nj]);
        }
    }

#pragma unroll
    for (int mi = 0; mi < 4; mi++) {
#pragma unroll
        for (int nj = 0; nj < 4; nj++) {
            int r0 = blockIdx.y * 128 + warp_m * 64 + mi * 16 + g;
            int c0 = blockIdx.x * 128 + warp_n * 32 + nj * 8 + 2 * t;
            *(float2*)(C + (size_t)r0 * N + c0) = make_float2(acc[mi][nj][0], acc[mi][nj][1]);
            *(float2*)(C + (size_t)(r0 + 8) * N + c0) = make_float2(acc[mi][nj][2], acc[mi][nj][3]);
        }
    }
}

// ---------------------------------------------------------------------------
// RoPE + f16 convert: reads f32 qkv, writes f16 qkvh (q,k roped; v plain).
// ---------------------------------------------------------------------------
__global__ void rope_f16_kernel(const float* __restrict__ qkv,
                                __half* __restrict__ qkvh,
                                const float* __restrict__ cosp,
                                const float* __restrict__ sinp)
{
    const int tk = blockIdx.x;
    const int hh = blockIdx.y;        // 0..47
    const int d = threadIdx.x;        // 0..63
    const int s = tk & (SEQ - 1);

    const float* p = qkv + (size_t)tk * NQKV + hh * HD;
    __half* ph = qkvh + (size_t)tk * NQKV + hh * HD;
    float x1 = p[d];
    float x2 = p[d + 64];
    if (hh < 2 * NH) {
        float c1 = cosp[s * HD + d];
        float c2 = cosp[s * HD + d + 64];
        float s1 = sinp[s * HD + d];
        float s2 = sinp[s * HD + d + 64];
        ph[d]      = __float2half_rn(x1 * c1 - x2 * s1);
        ph[d + 64] = __float2half_rn(x2 * c2 + x1 * s2);
    } else {
        ph[d]      = __float2half_rn(x1);
        ph[d + 64] = __float2half_rn(x2);
    }
}

// ---------------------------------------------------------------------------
// Flash attention fp16 (flash8): R12 pipeline skeleton, BQ=64, BKV=32,
// 4 warps, 2 CTAs/SM. K frags LDSM, V frags LDSM.trans, P packs to f16x2
// in-register (no shuffles). f32 accumulation & softmax.
// ---------------------------------------------------------------------------
#define F8_STRH 136
#define F8_BUFH (32 * F8_STRH)
#define FLASH8_SMEM (4 * F8_BUFH * 2)   // 34816 bytes
#define NTILE8 (SEQ / 32)

__global__ __launch_bounds__(128, 2) void flash8_f16(
    const __half* __restrict__ qkvh, __half* __restrict__ outh)
{
    extern __shared__ __half sfh[];
    const uint32_t sfb = smem_u32(sfh);

    const int tid = threadIdx.x;
    const int wid = tid >> 5;
    const int lane = tid & 31;
    const int g = lane >> 2;
    const int t = lane & 3;
    const unsigned FULL = 0xffffffffu;

    const int b = blockIdx.y >> 4;
    const int h = blockIdx.y & 15;
    const int q0 = blockIdx.x * 64;
    const float scale = 0.08838834764831845f;  // 1/sqrt(128)

    const __half* qbase = qkvh + (size_t)(b * SEQ + q0 + wid * 16) * NQKV + h * HD;
    const __half* kbase = qkvh + (size_t)(b * SEQ) * NQKV + (NH + h) * HD;
    const __half* vbase = qkvh + (size_t)(b * SEQ) * NQKV + (2 * NH + h) * HD;

    // Q fragments direct from gmem: qa[ks][0]=Q[g][2t..], [1]=g+8, [2]=k+8, [3]=g+8,k+8
    unsigned qa[8][4];
#pragma unroll
    for (int ks = 0; ks < 8; ks++) {
        int kk = ks * 16;
        qa[ks][0] = *(const unsigned*)(qbase + (size_t)g * NQKV + kk + 2 * t);
        qa[ks][1] = *(const unsigned*)(qbase + (size_t)(g + 8) * NQKV + kk + 2 * t);
        qa[ks][2] = *(const unsigned*)(qbase + (size_t)g * NQKV + kk + 8 + 2 * t);
        qa[ks][3] = *(const unsigned*)(qbase + (size_t)(g + 8) * NQKV + kk + 8 + 2 * t);
    }

    float oacc[16][4];
#pragma unroll
    for (int ni = 0; ni < 16; ni++)
#pragma unroll
        for (int r = 0; r < 4; r++) oacc[ni][r] = 0.f;

    float m0 = -INFINITY, m1 = -INFINITY, l0 = 0.f, l1 = 0.f;

    // K-frag lane addressing (B pattern, non-trans)
    const int k_row = (lane & 7) + ((lane >= 16) ? 8 : 0);
    const int k_cbh = ((lane >> 3) & 1) * 8;
    const uint32_t kfrag0 = sfb + (uint32_t)(k_row * F8_STRH + k_cbh) * 2;
    // V-frag lane addressing (trans)
    const int v_row = (lane & 7) + ((lane >> 3) & 1) * 8;
    const int v_cb = (lane >= 16) ? 1 : 0;

    float sa[4][4], sb[4][4];

    // 32 rows x 128 halfs = 512 16B-chunks; 128 thr x 4
#define F8_ISSUE(bufofs, base, kt)                                               \
    do {                                                                         \
        __half* buf_ = sfh + (bufofs);                                           \
        _Pragma("unroll")                                                        \
        for (int i = 0; i < 4; i++) {                                            \
            int idx = tid + 128 * i;                                             \
            int r_ = idx >> 4, c_ = (idx & 15) * 8;                              \
            cp16(&buf_[r_ * F8_STRH + c_],                                       \
                 (base) + (size_t)((kt) * 32 + r_) * NQKV + c_);                 \
        }                                                                        \
    } while (0)

#define F8_SMMA(S_, kt)                                                          \
    do {                                                                         \
        const uint32_t kfb_ = kfrag0 + (uint32_t)(((kt) & 1) * F8_BUFH) * 2;     \
        _Pragma("unroll")                                                        \
        for (int nj = 0; nj < 4; nj++)                                           \
            _Pragma("unroll")                                                    \
            for (int r = 0; r < 4; r++) S_[nj][r] = 0.f;                         \
        _Pragma("unroll")                                                        \
        for (int ks = 0; ks < 8; ks++) {                                         \
            const int kk = ks * 16;                                              \
            unsigned bn[4][2];                                                   \
            {                                                                    \
                unsigned r0, r1, r2, r3;                                         \
                ldsm_x4(r0, r1, r2, r3, kfb_ + (uint32_t)kk * 2);                \
                bn[0][0] = r0; bn[0][1] = r1; bn[1][0] = r2; bn[1][1] = r3;      \
                ldsm_x4(r0, r1, r2, r3, kfb_ + (uint32_t)(16 * F8_STRH + kk) * 2);\
                bn[2][0] = r0; bn[2][1] = r1; bn[3][0] = r2; bn[3][1] = r3;      \
            }                                                                    \
            _Pragma("unroll")                                                    \
            for (int nj = 0; nj < 4; nj++)                                       \
                mma_f16(S_[nj], qa[ks], bn[nj]);                                 \
        }                                                                        \
    } while (0)

#define F8_SOFTMAX(S_)                                                           \
    do {                                                                         \
        float mx0 = -INFINITY, mx1 = -INFINITY;                                  \
        _Pragma("unroll")                                                        \
        for (int j = 0; j < 4; j++) {                                            \
            S_[j][0] *= scale; S_[j][1] *= scale;                                \
            S_[j][2] *= scale; S_[j][3] *= scale;                                \
            mx0 = fmaxf(mx0, fmaxf(S_[j][0], S_[j][1]));                         \
            mx1 = fmaxf(mx1, fmaxf(S_[j][2], S_[j][3]));                         \
        }                                                                        \
        mx0 = fmaxf(mx0, __shfl_xor_sync(FULL, mx0, 1));                         \
        mx0 = fmaxf(mx0, __shfl_xor_sync(FULL, mx0, 2));                         \
        mx1 = fmaxf(mx1, __shfl_xor_sync(FULL, mx1, 1));                         \
        mx1 = fmaxf(mx1, __shfl_xor_sync(FULL, mx1, 2));                         \
        float mn0 = fmaxf(m0, mx0), mn1 = fmaxf(m1, mx1);                        \
        float a0 = __expf(m0 - mn0), a1 = __expf(m1 - mn1);                      \
        float s0 = 0.f, s1 = 0.f;                                                \
        _Pragma("unroll")                                                        \
        for (int j = 0; j < 4; j++) {                                            \
            S_[j][0] = __expf(S_[j][0] - mn0);                                   \
            S_[j][1] = __expf(S_[j][1] - mn0);                                   \
            S_[j][2] = __expf(S_[j][2] - mn1);                                   \
            S_[j][3] = __expf(S_[j][3] - mn1);                                   \
            s0 += S_[j][0] + S_[j][1];                                           \
            s1 += S_[j][2] + S_[j][3];                                           \
        }                                                                        \
        s0 += __shfl_xor_sync(FULL, s0, 1);                                      \
        s0 += __shfl_xor_sync(FULL, s0, 2);                                      \
        s1 += __shfl_xor_sync(FULL, s1, 1);                                      \
        s1 += __shfl_xor_sync(FULL, s1, 2);                                      \
        l0 = l0 * a0 + s0;                                                       \
        l1 = l1 * a1 + s1;                                                       \
        m0 = mn0; m1 = mn1;                                                      \
        if (a0 != 1.f || a1 != 1.f) {                                            \
            _Pragma("unroll")                                                    \
            for (int ni = 0; ni < 16; ni++) {                                    \
                oacc[ni][0] *= a0; oacc[ni][1] *= a0;                            \
                oacc[ni][2] *= a1; oacc[ni][3] *= a1;                            \
            }                                                                    \
        }                                                                        \
    } while (0)

#define F8_PV(S_, kt)                                                            \
    do {                                                                         \
        const uint32_t vsb_ = sfb + (uint32_t)((2 + ((kt) & 1)) * F8_BUFH) * 2;  \
        _Pragma("unroll")                                                        \
        for (int j2 = 0; j2 < 2; j2++) {                                         \
            unsigned pa[4];                                                      \
            pa[0] = pack_h2(S_[2*j2][0], S_[2*j2][1]);                           \
            pa[1] = pack_h2(S_[2*j2][2], S_[2*j2][3]);                           \
            pa[2] = pack_h2(S_[2*j2+1][0], S_[2*j2+1][1]);                       \
            pa[3] = pack_h2(S_[2*j2+1][2], S_[2*j2+1][3]);                       \
            const uint32_t vrow_ = vsb_ +                                        \
                (uint32_t)((j2 * 16 + v_row) * F8_STRH) * 2;                     \
            _Pragma("unroll")                                                    \
            for (int q2 = 0; q2 < 8; q2++) {                                     \
                unsigned r0, r1, r2, r3;                                         \
                ldsm_x4_t(r0, r1, r2, r3,                                        \
                          vrow_ + (uint32_t)((2 * q2 + v_cb) * 8) * 2);          \
                unsigned vv0[2] = {r0, r1};                                      \
                unsigned vv1[2] = {r2, r3};                                      \
                mma_f16(oacc[2 * q2], pa, vv0);                                  \
                mma_f16(oacc[2 * q2 + 1], pa, vv1);                              \
            }                                                                    \
        }                                                                        \
    } while (0)

#define F8_STEP(CUR, NXT, kt)                                                    \
    do {                                                                         \
        cp_wait<1>(); __syncthreads();            /* K(kt+1) ready */            \
        if ((kt) + 1 < NTILE8) {                                                 \
            F8_SMMA(NXT, (kt) + 1);                                              \
            if ((kt) + 2 < NTILE8)                                               \
                F8_ISSUE(((kt) & 1) * F8_BUFH, kbase, (kt) + 2);                 \
        }                                                                        \
        cp_commit();                                                             \
        F8_SOFTMAX(CUR);                                                         \
        cp_wait<1>(); __syncthreads();            /* V(kt) ready */              \
        F8_PV(CUR, kt);                                                          \
        if ((kt) + 1 < NTILE8)                                                   \
            F8_ISSUE((2 + (((kt) + 1) & 1)) * F8_BUFH, vbase, (kt) + 1);         \
        cp_commit();                                                             \
    } while (0)

    // prologue: K0 -> wait -> S(0) -> issue K1, V0
    F8_ISSUE(0, kbase, 0); cp_commit();
    cp_wait<0>(); __syncthreads();
    F8_SMMA(sa, 0);
    __syncthreads();                                // all warps done reading K0
    F8_ISSUE(F8_BUFH, kbase, 1); cp_commit();       // K1
    F8_ISSUE(2 * F8_BUFH, vbase, 0); cp_commit();   // V0

    for (int kt = 0; kt < NTILE8; kt += 2) {
        F8_STEP(sa, sb, kt);
        F8_STEP(sb, sa, kt + 1);
    }

    // ---- epilogue: normalize + f16 write ----
    float li0 = 1.0f / l0, li1 = 1.0f / l1;
    const int r0 = q0 + wid * 16 + g;
    __half* o0 = outh + (size_t)(b * SEQ + r0) * (NH * HD) + h * HD;
    __half* o1 = outh + (size_t)(b * SEQ + r0 + 8) * (NH * HD) + h * HD;
#pragma unroll
    for (int ni = 0; ni < 16; ni++) {
        int nc = ni * 8 + 2 * t;
        *(unsigned*)(o0 + nc) = pack_h2(oacc[ni][0] * li0, oacc[ni][1] * li0);
        *(unsigned*)(o1 + nc) = pack_h2(oacc[ni][2] * li1, oacc[ni][3] * li1);
    }
}

// ---------------------------------------------------------------------------
extern "C" void kernel_launch(void* const* d_in, const int* in_sizes, int n_in,
                              void* d_out, int out_size)
{
    const float* hidden = (const float*)d_in[0];
    const float* cosp   = (const float*)d_in[1];
    const float* sinp   = (const float*)d_in[2];
    const float* wqkv   = (const float*)d_in[3];
    const float* wo     = (const float*)d_in[4];
    float* out = (float*)d_out;

    void *p0, *p1, *p2, *p3, *p4, *p5;
    cudaGetSymbolAddress(&p0, g_qkv);
    cudaGetSymbolAddress(&p1, g_qkvh);
    cudaGetSymbolAddress(&p2, g_attnh);
    cudaGetSymbolAddress(&p3, g_hidh);
    cudaGetSymbolAddress(&p4, g_wqkvh);
    cudaGetSymbolAddress(&p5, g_woh);
    float*  qkv    = (float*)p0;
    __half* qkvh   = (__half*)p1;
    __half* attnh  = (__half*)p2;
    __half* hidh   = (__half*)p3;
    __half* wqkvh  = (__half*)p4;
    __half* woh    = (__half*)p5;

    static bool attr_set = false;
    if (!attr_set) {
        cudaFuncSetAttribute(flash8_f16, cudaFuncAttributeMaxDynamicSharedMemorySize, FLASH8_SMEM);
        cudaFuncSetAttribute(gemm_f16, cudaFuncAttributeMaxDynamicSharedMemorySize, GEMM_SMEM);
        attr_set = true;
    }

    dim3 tpb(32, 8);

    // 0) prep: hidden -> f16; weights transpose+convert to [N][K] f16
    {
        int n4h = NTOK * DM / 4;
        round_f16_kernel<<<n4h / 256, 256>>>((const float4*)hidden, (uint2*)hidh, n4h);
        transpose_f16_kernel<<<dim3(NQKV / 32, DM / 32), tpb>>>(wqkv, wqkvh, DM, NQKV);
        transpose_f16_kernel<<<dim3(DM / 32, DM / 32), tpb>>>(wo, woh, DM, DM);
    }
    // 1) QKV projection (fp16 in, fp32 out)
    {
        dim3 grid(NQKV / 128, NTOK / 128);   // 48 x 32
        gemm_f16<<<grid, 256, GEMM_SMEM>>>(hidh, wqkvh, qkv, NTOK, NQKV, DM);
    }
    // 2) RoPE + f16 convert
    {
        dim3 grid(NTOK, 3 * NH);
        rope_f16_kernel<<<grid, 64>>>(qkv, qkvh, cosp, sinp);
    }
    // 3) Flash attention (fp16)
    {
        dim3 grid(SEQ / 64, BATCH * NH);   // 32 x 32
        flash8_f16<<<grid, 128, FLASH8_SMEM>>>(qkvh, attnh);
    }
    // 4) Output projection (fp16 in, fp32 out)
    {
        dim3 grid(DM / 128, NTOK / 128);   // 16 x 32
        gemm_f16<<<grid, 256, GEMM_SMEM>>>(attnh, woh, out, NTOK, DM, NH * HD);
    }
}

// round 16
// speedup vs baseline: 1.8530x; 1.0148x over previous
#include <cuda_runtime.h>
#include <cuda_fp16.h>
#include <math.h>
#include <stdint.h>

// Problem constants
#define BATCH 2
#define SEQ 2048
#define DM 2048
#define NH 16
#define HD 128
#define NQKV ((NH + 2*NH) * HD)   // 6144
#define NTOK (BATCH * SEQ)        // 4096

// Scratch (allocation-free rule: __device__ globals)
__device__ float  g_qkv[(size_t)NTOK * NQKV];        // 96 MB (f32 gemm out)
__device__ __half g_qkvh[(size_t)NTOK * NQKV];       // 48 MB (roped fp16)
__device__ __half g_attnh[(size_t)NTOK * (NH * HD)]; // 16 MB
__device__ __half g_hidh[(size_t)NTOK * DM];         // 16 MB
__device__ __half g_wqkvh[(size_t)DM * NQKV];        // 24 MB [N][K]
__device__ __half g_woh[(size_t)DM * DM];            //  8 MB [N][K]

// ---------------------------------------------------------------------------
// helpers
// ---------------------------------------------------------------------------
__device__ __forceinline__ unsigned pack_h2(float lo, float hi) {
    unsigned d;
    asm("cvt.rn.f16x2.f32 %0, %1, %2;" : "=r"(d) : "f"(hi), "f"(lo));
    return d;
}

__device__ __forceinline__ void mma_f16(float* c, const unsigned* a, const unsigned* b) {
    asm volatile(
        "mma.sync.aligned.m16n8k16.row.col.f32.f16.f16.f32 "
        "{%0,%1,%2,%3}, {%4,%5,%6,%7}, {%8,%9}, {%0,%1,%2,%3};"
        : "+f"(c[0]), "+f"(c[1]), "+f"(c[2]), "+f"(c[3])
        : "r"(a[0]), "r"(a[1]), "r"(a[2]), "r"(a[3]), "r"(b[0]), "r"(b[1]));
}

__device__ __forceinline__ void cp16(void* dst_smem, const void* src) {
    unsigned d = (unsigned)__cvta_generic_to_shared(dst_smem);
    asm volatile("cp.async.cg.shared.global [%0], [%1], 16;" :: "r"(d), "l"(src));
}
__device__ __forceinline__ void cp_commit() {
    asm volatile("cp.async.commit_group;");
}
template<int N>
__device__ __forceinline__ void cp_wait() {
    asm volatile("cp.async.wait_group %0;" :: "n"(N));
}
__device__ __forceinline__ uint32_t smem_u32(const void* p) {
    uint32_t a;
    asm("{ .reg .u64 t; cvta.to.shared.u64 t, %1; cvt.u32.u64 %0, t; }" : "=r"(a) : "l"(p));
    return a;
}
__device__ __forceinline__ void ldsm_x4(unsigned& r0, unsigned& r1, unsigned& r2,
                                        unsigned& r3, uint32_t addr) {
    asm volatile("ldmatrix.sync.aligned.m8n8.x4.shared.b16 {%0,%1,%2,%3}, [%4];"
                 : "=r"(r0), "=r"(r1), "=r"(r2), "=r"(r3) : "r"(addr));
}
__device__ __forceinline__ void ldsm_x4_t(unsigned& r0, unsigned& r1, unsigned& r2,
                                          unsigned& r3, uint32_t addr) {
    asm volatile("ldmatrix.sync.aligned.m8n8.x4.trans.shared.b16 {%0,%1,%2,%3}, [%4];"
                 : "=r"(r0), "=r"(r1), "=r"(r2), "=r"(r3) : "r"(addr));
}

// ---------------------------------------------------------------------------
// f32 -> f16 conversion (vectorized)
// ---------------------------------------------------------------------------
__global__ void round_f16_kernel(const float4* __restrict__ in,
                                 uint2* __restrict__ out, int n4)
{
    int i = blockIdx.x * 256 + threadIdx.x;
    if (i < n4) {
        float4 v = in[i];
        out[i] = make_uint2(pack_h2(v.x, v.y), pack_h2(v.z, v.w));
    }
}

// ---------------------------------------------------------------------------
// transpose + f16 convert: in f32 [R][C] -> out f16 [C][R]
// ---------------------------------------------------------------------------
__global__ void transpose_f16_kernel(const float* __restrict__ in,
                                     __half* __restrict__ out, int R, int C)
{
    __shared__ float tile[32][33];
    const int c0 = blockIdx.x * 32;
    const int r0 = blockIdx.y * 32;
    const int tx = threadIdx.x;
#pragma unroll
    for (int i = threadIdx.y; i < 32; i += 8)
        tile[i][tx] = in[(size_t)(r0 + i) * C + c0 + tx];
    __syncthreads();
#pragma unroll
    for (int i = threadIdx.y; i < 32; i += 8)
        out[(size_t)(c0 + i) * R + r0 + tx] = __float2half_rn(tile[tx][i]);
}

// ---------------------------------------------------------------------------
// FP16 GEMM: C[M,N](f32) = A[M,K](f16) * B[N,K](f16)^T
//   CTA tile 128x128x64, 3-stage cp.async, 256 threads, 2 CTA/SM,
//   LDSM fragments, mma m16n8k16.
// ---------------------------------------------------------------------------
#define GSTRH 72
#define STG_H (2 * 128 * GSTRH)            // halfs per stage (A then B)
#define GEMM_SMEM (3 * STG_H * 2)          // 110592 bytes

__global__ __launch_bounds__(256, 2) void gemm_f16(
    const __half* __restrict__ A, const __half* __restrict__ B,
    float* __restrict__ C, int M, int N, int K)
{
    extern __shared__ __half smh[];
    const uint32_t smb = smem_u32(smh);

    const int tid = threadIdx.x;
    const int wid = tid >> 5;
    const int lane = tid & 31;
    const int g = lane >> 2;
    const int t = lane & 3;
    const int warp_m = wid & 1;
    const int warp_n = wid >> 1;

    const __half* Ab = A + (size_t)(blockIdx.y * 128) * K;
    const __half* Bb = B + (size_t)(blockIdx.x * 128) * K;

    float acc[4][4][4];
#pragma unroll
    for (int mi = 0; mi < 4; mi++)
#pragma unroll
        for (int nj = 0; nj < 4; nj++)
#pragma unroll
            for (int r = 0; r < 4; r++) acc[mi][nj][r] = 0.f;

    const int KT = K >> 6;

#define GEMM_ISSUE(stage, kt)                                                   \
    do {                                                                        \
        __half* as_ = smh + (stage) * STG_H;                                    \
        __half* bs_ = as_ + 128 * GSTRH;                                        \
        const __half* ag_ = Ab + (size_t)(kt) * 64;                             \
        const __half* bg_ = Bb + (size_t)(kt) * 64;                             \
        _Pragma("unroll")                                                       \
        for (int i = 0; i < 4; i++) {                                           \
            int idx = tid + 256 * i;                                            \
            int r_ = idx >> 3, c_ = (idx & 7) * 8;                              \
            cp16(&as_[r_ * GSTRH + c_], ag_ + (size_t)r_ * K + c_);             \
            cp16(&bs_[r_ * GSTRH + c_], bg_ + (size_t)r_ * K + c_);             \
        }                                                                       \
    } while (0)

    GEMM_ISSUE(0, 0); cp_commit();
    GEMM_ISSUE(1, 1); cp_commit();

    const int a_row = (lane & 7) + ((lane >> 3) & 1) * 8;
    const int a_colh = (lane >= 16) ? 8 : 0;
    const int b_row = (lane & 7) + ((lane >= 16) ? 8 : 0);
    const int b_colh = ((lane >> 3) & 1) * 8;

    for (int kt = 0; kt < KT; kt++) {
        cp_wait<1>();
        __syncthreads();

        if (kt + 2 < KT) GEMM_ISSUE((kt + 2) % 3, kt + 2);
        cp_commit();

        const uint32_t as_u = smb + ((kt % 3) * STG_H) * 2;
        const uint32_t bs_u = as_u + 128 * GSTRH * 2;
        const uint32_t abase = as_u + (uint32_t)((warp_m * 64 + a_row) * GSTRH + a_colh) * 2;
        const uint32_t bbase = bs_u + (uint32_t)((warp_n * 32 + b_row) * GSTRH + b_colh) * 2;

#pragma unroll
        for (int ks = 0; ks < 4; ks++) {
            const int kk = ks * 16;
            unsigned am[4][4], bn[4][2];
#pragma unroll
            for (int mi = 0; mi < 4; mi++)
                ldsm_x4(am[mi][0], am[mi][1], am[mi][2], am[mi][3],
                        abase + (uint32_t)(mi * 16 * GSTRH + kk) * 2);
            {
                unsigned r0, r1, r2, r3;
                ldsm_x4(r0, r1, r2, r3, bbase + (uint32_t)kk * 2);
                bn[0][0] = r0; bn[0][1] = r1; bn[1][0] = r2; bn[1][1] = r3;
                ldsm_x4(r0, r1, r2, r3, bbase + (uint32_t)(16 * GSTRH + kk) * 2);
                bn[2][0] = r0; bn[2][1] = r1; bn[3][0] = r2; bn[3][1] = r3;
            }
#pragma unroll
            for (int mi = 0; mi < 4; mi++)
#pragma unroll
                for (int nj = 0; nj < 4; nj++)
                    mma_f16(acc[mi][nj], am[mi], bn[nj]);
        }
    }

#pragma unroll
    for (int mi = 0; mi < 4; mi++) {
#pragma unroll
        for (int nj = 0; nj < 4; nj++) {
            int r0 = blockIdx.y * 128 + warp_m * 64 + mi * 16 + g;
            int c0 = blockIdx.x * 128 + warp_n * 32 + nj * 8 + 2 * t;
            *(float2*)(C + (size_t)r0 * N + c0) = make_float2(acc[mi][nj][0], acc[mi][nj][1]);
            *(float2*)(C + (size_t)(r0 + 8) * N + c0) = make_float2(acc[mi][nj][2], acc[mi][nj][3]);
        }
    }
}

// ---------------------------------------------------------------------------
// RoPE + f16 convert: reads f32 qkv, writes f16 qkvh (q,k roped; v plain).
// ---------------------------------------------------------------------------
__global__ void rope_f16_kernel(const float* __restrict__ qkv,
                                __half* __restrict__ qkvh,
                                const float* __restrict__ cosp,
                                const float* __restrict__ sinp)
{
    const int tk = blockIdx.x;
    const int hh = blockIdx.y;        // 0..47
    const int d = threadIdx.x;        // 0..63
    const int s = tk & (SEQ - 1);

    const float* p = qkv + (size_t)tk * NQKV + hh * HD;
    __half* ph = qkvh + (size_t)tk * NQKV + hh * HD;
    float x1 = p[d];
    float x2 = p[d + 64];
    if (hh < 2 * NH) {
        float c1 = cosp[s * HD + d];
        float c2 = cosp[s * HD + d + 64];
        float s1 = sinp[s * HD + d];
        float s2 = sinp[s * HD + d + 64];
        ph[d]      = __float2half_rn(x1 * c1 - x2 * s1);
        ph[d + 64] = __float2half_rn(x2 * c2 + x1 * s2);
    } else {
        ph[d]      = __float2half_rn(x1);
        ph[d + 64] = __float2half_rn(x2);
    }
}

// ---------------------------------------------------------------------------
// Flash attention fp16 (flash8): BQ=64, BKV=32, 4 warps, 3 CTAs/SM.
// K frags LDSM, V frags LDSM.trans, P packs to f16x2 in-register.
// ---------------------------------------------------------------------------
#define F8_STRH 136
#define F8_BUFH (32 * F8_STRH)
#define FLASH8_SMEM (4 * F8_BUFH * 2)   // 34816 bytes
#define NTILE8 (SEQ / 32)

__global__ __launch_bounds__(128, 3) void flash8_f16(
    const __half* __restrict__ qkvh, __half* __restrict__ outh)
{
    extern __shared__ __half sfh[];
    const uint32_t sfb = smem_u32(sfh);

    const int tid = threadIdx.x;
    const int wid = tid >> 5;
    const int lane = tid & 31;
    const int g = lane >> 2;
    const int t = lane & 3;
    const unsigned FULL = 0xffffffffu;

    const int b = blockIdx.y >> 4;
    const int h = blockIdx.y & 15;
    const int q0 = blockIdx.x * 64;
    const float scale = 0.08838834764831845f;  // 1/sqrt(128)

    const __half* qbase = qkvh + (size_t)(b * SEQ + q0 + wid * 16) * NQKV + h * HD;
    const __half* kbase = qkvh + (size_t)(b * SEQ) * NQKV + (NH + h) * HD;
    const __half* vbase = qkvh + (size_t)(b * SEQ) * NQKV + (2 * NH + h) * HD;

    unsigned qa[8][4];
#pragma unroll
    for (int ks = 0; ks < 8; ks++) {
        int kk = ks * 16;
        qa[ks][0] = *(const unsigned*)(qbase + (size_t)g * NQKV + kk + 2 * t);
        qa[ks][1] = *(const unsigned*)(qbase + (size_t)(g + 8) * NQKV + kk + 2 * t);
        qa[ks][2] = *(const unsigned*)(qbase + (size_t)g * NQKV + kk + 8 + 2 * t);
        qa[ks][3] = *(const unsigned*)(qbase + (size_t)(g + 8) * NQKV + kk + 8 + 2 * t);
    }

    float oacc[16][4];
#pragma unroll
    for (int ni = 0; ni < 16; ni++)
#pragma unroll
        for (int r = 0; r < 4; r++) oacc[ni][r] = 0.f;

    float m0 = -INFINITY, m1 = -INFINITY, l0 = 0.f, l1 = 0.f;

    const int k_row = (lane & 7) + ((lane >= 16) ? 8 : 0);
    const int k_cbh = ((lane >> 3) & 1) * 8;
    const uint32_t kfrag0 = sfb + (uint32_t)(k_row * F8_STRH + k_cbh) * 2;
    const int v_row = (lane & 7) + ((lane >> 3) & 1) * 8;
    const int v_cb = (lane >= 16) ? 1 : 0;

    float sa[4][4], sb[4][4];

#define F8_ISSUE(bufofs, base, kt)                                               \
    do {                                                                         \
        __half* buf_ = sfh + (bufofs);                                           \
        _Pragma("unroll")                                                        \
        for (int i = 0; i < 4; i++) {                                            \
            int idx = tid + 128 * i;                                             \
            int r_ = idx >> 4, c_ = (idx & 15) * 8;                              \
            cp16(&buf_[r_ * F8_STRH + c_],                                       \
                 (base) + (size_t)((kt) * 32 + r_) * NQKV + c_);                 \
        }                                                                        \
    } while (0)

#define F8_SMMA(S_, kt)                                                          \
    do {                                                                         \
        const uint32_t kfb_ = kfrag0 + (uint32_t)(((kt) & 1) * F8_BUFH) * 2;     \
        _Pragma("unroll")                                                        \
        for (int nj = 0; nj < 4; nj++)                                           \
            _Pragma("unroll")                                                    \
            for (int r = 0; r < 4; r++) S_[nj][r] = 0.f;                         \
        _Pragma("unroll")                                                        \
        for (int ks = 0; ks < 8; ks++) {                                         \
            const int kk = ks * 16;                                              \
            unsigned bn[4][2];                                                   \
            {                                                                    \
                unsigned r0, r1, r2, r3;                                         \
                ldsm_x4(r0, r1, r2, r3, kfb_ + (uint32_t)kk * 2);                \
                bn[0][0] = r0; bn[0][1] = r1; bn[1][0] = r2; bn[1][1] = r3;      \
                ldsm_x4(r0, r1, r2, r3, kfb_ + (uint32_t)(16 * F8_STRH + kk) * 2);\
                bn[2][0] = r0; bn[2][1] = r1; bn[3][0] = r2; bn[3][1] = r3;      \
            }                                                                    \
            _Pragma("unroll")                                                    \
            for (int nj = 0; nj < 4; nj++)                                       \
                mma_f16(S_[nj], qa[ks], bn[nj]);                                 \
        }                                                                        \
    } while (0)

#define F8_SOFTMAX(S_)                                                           \
    do {                                                                         \
        float mx0 = -INFINITY, mx1 = -INFINITY;                                  \
        _Pragma("unroll")                                                        \
        for (int j = 0; j < 4; j++) {                                            \
            S_[j][0] *= scale; S_[j][1] *= scale;                                \
            S_[j][2] *= scale; S_[j][3] *= scale;                                \
            mx0 = fmaxf(mx0, fmaxf(S_[j][0], S_[j][1]));                         \
            mx1 = fmaxf(mx1, fmaxf(S_[j][2], S_[j][3]));                         \
        }                                                                        \
        mx0 = fmaxf(mx0, __shfl_xor_sync(FULL, mx0, 1));                         \
        mx0 = fmaxf(mx0, __shfl_xor_sync(FULL, mx0, 2));                         \
        mx1 = fmaxf(mx1, __shfl_xor_sync(FULL, mx1, 1));                         \
        mx1 = fmaxf(mx1, __shfl_xor_sync(FULL, mx1, 2));                         \
        float mn0 = fmaxf(m0, mx0), mn1 = fmaxf(m1, mx1);                        \
        float a0 = __expf(m0 - mn0), a1 = __expf(m1 - mn1);                      \
        float s0 = 0.f, s1 = 0.f;                                                \
        _Pragma("unroll")                                                        \
        for (int j = 0; j < 4; j++) {                                            \
            S_[j][0] = __expf(S_[j][0] - mn0);                                   \
            S_[j][1] = __expf(S_[j][1] - mn0);                                   \
            S_[j][2] = __expf(S_[j][2] - mn1);                                   \
            S_[j][3] = __expf(S_[j][3] - mn1);                                   \
            s0 += S_[j][0] + S_[j][1];                                           \
            s1 += S_[j][2] + S_[j][3];                                           \
        }                                                                        \
        s0 += __shfl_xor_sync(FULL, s0, 1);                                      \
        s0 += __shfl_xor_sync(FULL, s0, 2);                                      \
        s1 += __shfl_xor_sync(FULL, s1, 1);                                      \
        s1 += __shfl_xor_sync(FULL, s1, 2);                                      \
        l0 = l0 * a0 + s0;                                                       \
        l1 = l1 * a1 + s1;                                                       \
        m0 = mn0; m1 = mn1;                                                      \
        if (a0 != 1.f || a1 != 1.f) {                                            \
            _Pragma("unroll")                                                    \
            for (int ni = 0; ni < 16; ni++) {                                    \
                oacc[ni][0] *= a0; oacc[ni][1] *= a0;                            \
                oacc[ni][2] *= a1; oacc[ni][3] *= a1;                            \
            }                                                                    \
        }                                                                        \
    } while (0)

#define F8_PV(S_, kt)                                                            \
    do {                                                                         \
        const uint32_t vsb_ = sfb + (uint32_t)((2 + ((kt) & 1)) * F8_BUFH) * 2;  \
        _Pragma("unroll")                                                        \
        for (int j2 = 0; j2 < 2; j2++) {                                         \
            unsigned pa[4];                                                      \
            pa[0] = pack_h2(S_[2*j2][0], S_[2*j2][1]);                           \
            pa[1] = pack_h2(S_[2*j2][2], S_[2*j2][3]);                           \
            pa[2] = pack_h2(S_[2*j2+1][0], S_[2*j2+1][1]);                       \
            pa[3] = pack_h2(S_[2*j2+1][2], S_[2*j2+1][3]);                       \
            const uint32_t vrow_ = vsb_ +                                        \
                (uint32_t)((j2 * 16 + v_row) * F8_STRH) * 2;                     \
            _Pragma("unroll")                                                    \
            for (int q2 = 0; q2 < 8; q2++) {                                     \
                unsigned r0, r1, r2, r3;                                         \
                ldsm_x4_t(r0, r1, r2, r3,                                        \
                          vrow_ + (uint32_t)((2 * q2 + v_cb) * 8) * 2);          \
                unsigned vv0[2] = {r0, r1};                                      \
                unsigned vv1[2] = {r2, r3};                                      \
                mma_f16(oacc[2 * q2], pa, vv0);                                  \
                mma_f16(oacc[2 * q2 + 1], pa, vv1);                              \
            }                                                                    \
        }                                                                        \
    } while (0)

#define F8_STEP(CUR, NXT, kt)                                                    \
    do {                                                                         \
        cp_wait<1>(); __syncthreads();            /* K(kt+1) ready */            \
        if ((kt) + 1 < NTILE8) {                                                 \
            F8_SMMA(NXT, (kt) + 1);                                              \
            if ((kt) + 2 < NTILE8)                                               \
                F8_ISSUE(((kt) & 1) * F8_BUFH, kbase, (kt) + 2);                 \
        }                                                                        \
        cp_commit();                                                             \
        F8_SOFTMAX(CUR);                                                         \
        cp_wait<1>(); __syncthreads();            /* V(kt) ready */              \
        F8_PV(CUR, kt);                                                          \
        if ((kt) + 1 < NTILE8)                                                   \
            F8_ISSUE((2 + (((kt) + 1) & 1)) * F8_BUFH, vbase, (kt) + 1);         \
        cp_commit();                                                             \
    } while (0)

    // prologue: K0 -> wait -> S(0) -> issue K1, V0
    F8_ISSUE(0, kbase, 0); cp_commit();
    cp_wait<0>(); __syncthreads();
    F8_SMMA(sa, 0);
    __syncthreads();                                // all warps done reading K0
    F8_ISSUE(F8_BUFH, kbase, 1); cp_commit();       // K1
    F8_ISSUE(2 * F8_BUFH, vbase, 0); cp_commit();   // V0

    for (int kt = 0; kt < NTILE8; kt += 2) {
        F8_STEP(sa, sb, kt);
        F8_STEP(sb, sa, kt + 1);
    }

    // ---- epilogue: normalize + f16 write ----
    float li0 = 1.0f / l0, li1 = 1.0f / l1;
    const int r0 = q0 + wid * 16 + g;
    __half* o0 = outh + (size_t)(b * SEQ + r0) * (NH * HD) + h * HD;
    __half* o1 = outh + (size_t)(b * SEQ + r0 + 8) * (NH * HD) + h * HD;
#pragma unroll
    for (int ni = 0; ni < 16; ni++) {
        int nc = ni * 8 + 2 * t;
        *(unsigned*)(o0 + nc) = pack_h2(oacc[ni][0] * li0, oacc[ni][1] * li0);
        *(unsigned*)(o1 + nc) = pack_h2(oacc[ni][2] * li1, oacc[ni][3] * li1);
    }
}

// ---------------------------------------------------------------------------
extern "C" void kernel_launch(void* const* d_in, const int* in_sizes, int n_in,
                              void* d_out, int out_size)
{
    const float* hidden = (const float*)d_in[0];
    const float* cosp   = (const float*)d_in[1];
    const float* sinp   = (const float*)d_in[2];
    const float* wqkv   = (const float*)d_in[3];
    const float* wo     = (const float*)d_in[4];
    float* out = (float*)d_out;

    void *p0, *p1, *p2, *p3, *p4, *p5;
    cudaGetSymbolAddress(&p0, g_qkv);
    cudaGetSymbolAddress(&p1, g_qkvh);
    cudaGetSymbolAddress(&p2, g_attnh);
    cudaGetSymbolAddress(&p3, g_hidh);
    cudaGetSymbolAddress(&p4, g_wqkvh);
    cudaGetSymbolAddress(&p5, g_woh);
    float*  qkv    = (float*)p0;
    __half* qkvh   = (__half*)p1;
    __half* attnh  = (__half*)p2;
    __half* hidh   = (__half*)p3;
    __half* wqkvh  = (__half*)p4;
    __half* woh    = (__half*)p5;

    static bool attr_set = false;
    if (!attr_set) {
        cudaFuncSetAttribute(flash8_f16, cudaFuncAttributeMaxDynamicSharedMemorySize, FLASH8_SMEM);
        cudaFuncSetAttribute(gemm_f16, cudaFuncAttributeMaxDynamicSharedMemorySize, GEMM_SMEM);
        attr_set = true;
    }

    dim3 tpb(32, 8);

    // 0) prep: hidden -> f16; weights transpose+convert to [N][K] f16
    {
        int n4h = NTOK * DM / 4;
        round_f16_kernel<<<n4h / 256, 256>>>((const float4*)hidden, (uint2*)hidh, n4h);
        transpose_f16_kernel<<<dim3(NQKV / 32, DM / 32), tpb>>>(wqkv, wqkvh, DM, NQKV);
        transpose_f16_kernel<<<dim3(DM / 32, DM / 32), tpb>>>(wo, woh, DM, DM);
    }
    // 1) QKV projection (fp16 in, fp32 out)
    {
        dim3 grid(NQKV / 128, NTOK / 128);   // 48 x 32
        gemm_f16<<<grid, 256, GEMM_SMEM>>>(hidh, wqkvh, qkv, NTOK, NQKV, DM);
    }
    // 2) RoPE + f16 convert
    {
        dim3 grid(NTOK, 3 * NH);
        rope_f16_kernel<<<grid, 64>>>(qkv, qkvh, cosp, sinp);
    }
    // 3) Flash attention (fp16, 3 CTAs/SM)
    {
        dim3 grid(SEQ / 64, BATCH * NH);   // 32 x 32
        flash8_f16<<<grid, 128, FLASH8_SMEM>>>(qkvh, attnh);
    }
    // 4) Output projection (fp16 in, fp32 out)
    {
        dim3 grid(DM / 128, NTOK / 128);   // 16 x 32
        gemm_f16<<<grid, 256, GEMM_SMEM>>>(attnh, woh, out, NTOK, DM, NH * HD);
    }
}